// round 16
// baseline (speedup 1.0000x reference)
#include <cuda_runtime.h>
#include <cuda_fp16.h>
#include <cstdint>

#define NB   4
#define SQL  2048
#define SKL  2048
#define DIM  512
#define RAD  128
#define NREL 257
#define NRELP 384   // padded

// ---------------- device scratch ----------------
__device__ float g_qrel[(size_t)NB * SQL * NRELP];
__device__ __half g_Qh[(size_t)NB * SQL * DIM];
__device__ __half g_Kh[(size_t)NB * SKL * DIM];
__device__ __half g_REh[(size_t)NRELP * DIM];
__device__ __half g_Vth[(size_t)NB * DIM * SKL];     // V^T
__device__ __half g_Ah[(size_t)NB * SQL * SKL];      // energies, then attn (fp16)

// ---------------- helpers ----------------
__device__ __forceinline__ uint32_t smem_u32(const void* p) {
    return (uint32_t)__cvta_generic_to_shared(p);
}

#define CP16(saddr, gptr) \
    asm volatile("cp.async.cg.shared.global [%0], [%1], 16;" :: "r"(saddr), "l"(gptr))
#define CP_COMMIT() asm volatile("cp.async.commit_group;")
#define CP_WAIT0()  asm volatile("cp.async.wait_group 0;" ::: "memory")

#define MMA_F16(d, a0, a1, a2, a3, b0, b1)                                        \
    asm volatile(                                                                 \
        "mma.sync.aligned.m16n8k16.row.col.f32.f16.f16.f32 "                      \
        "{%0,%1,%2,%3},{%4,%5,%6,%7},{%8,%9},{%0,%1,%2,%3};"                      \
        : "+f"((d)[0]), "+f"((d)[1]), "+f"((d)[2]), "+f"((d)[3])                  \
        : "r"(a0), "r"(a1), "r"(a2), "r"(a3), "r"(b0), "r"(b1))

#define LDSM_X4(r0, r1, r2, r3, addr)                                             \
    asm volatile("ldmatrix.sync.aligned.m8n8.x4.shared.b16 {%0,%1,%2,%3},[%4];"   \
        : "=r"(r0), "=r"(r1), "=r"(r2), "=r"(r3) : "r"(addr))

// ---------------------------------------------------------------------------
// fp32 -> fp16, 8 elems/thread vectorized (Q, K)
// ---------------------------------------------------------------------------
__global__ void __launch_bounds__(256) split_h_kernel(const float* __restrict__ x,
                                                      __half* __restrict__ hi) {
    const size_t i = ((size_t)blockIdx.x * 256 + threadIdx.x) * 8;
    float4 v0 = *(const float4*)(x + i);
    float4 v1 = *(const float4*)(x + i + 4);
    __half h[8];
    h[0] = __float2half(v0.x); h[1] = __float2half(v0.y);
    h[2] = __float2half(v0.z); h[3] = __float2half(v0.w);
    h[4] = __float2half(v1.x); h[5] = __float2half(v1.y);
    h[6] = __float2half(v1.z); h[7] = __float2half(v1.w);
    *(uint4*)(hi + i) = *(uint4*)h;
}

// RE [257,512] -> padded [384,512] (rows >=257 zero)
__global__ void __launch_bounds__(128) split_re_kernel(const float* __restrict__ RE,
                                                       __half* __restrict__ REh) {
    const int row = blockIdx.x;
    const int c = threadIdx.x * 4;
    __half h[4] = {};
    if (row < NREL) {
        float4 v = *(const float4*)(RE + (size_t)row * DIM + c);
        h[0] = __float2half(v.x); h[1] = __float2half(v.y);
        h[2] = __float2half(v.z); h[3] = __float2half(v.w);
    }
    *(float2*)(REh + (size_t)row * DIM + c) = *(float2*)h;
}

// ---------------------------------------------------------------------------
// V [b][k][n] -> Vt [b][n][k] fp16, 64x64 tile, vectorized
// ---------------------------------------------------------------------------
__global__ void __launch_bounds__(256) split_v_t_kernel(const float* __restrict__ V,
                                                        __half* __restrict__ Vth) {
    __shared__ float t[64][65];
    const int b = blockIdx.z;
    const int k0 = blockIdx.x * 64;
    const int n0 = blockIdx.y * 64;
    const int tid = threadIdx.x;
    const float* Vb = V + (size_t)b * SKL * DIM;

    #pragma unroll
    for (int p = 0; p < 4; p++) {
        int task = tid + p * 256;
        int k = task >> 4;
        int c4 = (task & 15) << 2;
        float4 v = *(const float4*)(Vb + (size_t)(k0 + k) * DIM + n0 + c4);
        t[k][c4] = v.x; t[k][c4 + 1] = v.y; t[k][c4 + 2] = v.z; t[k][c4 + 3] = v.w;
    }
    __syncthreads();

    __half* out = Vth + (size_t)b * DIM * SKL;
    #pragma unroll
    for (int p = 0; p < 2; p++) {
        int task = tid + p * 256;
        int n = task >> 3;
        int kg = (task & 7) << 3;
        __half h[8];
        #pragma unroll
        for (int r = 0; r < 8; r++) h[r] = __float2half(t[kg + r][n]);
        *(uint4*)(out + (size_t)(n0 + n) * SKL + k0 + kg) = *(uint4*)h;
    }
}

// ---------------------------------------------------------------------------
// Tensor-core GEMM, fp16, 1 term: C[m][n] = sum_k A[m,k]*B[n,k]
// 128x128x64 stages, 8 warps (warp 64x32), 2 CTA/SM, cp.async double buffer.
// Row pad 72 elems (144 B): 8 rows cover all 32 banks -> LDSM conflict-free.
// SCORES: writes fp16 energies (with relpos + scale) to Ce. Else fp32 to C.
// ---------------------------------------------------------------------------
#define ROWLEN 72
#define MATH   (128 * ROWLEN)          // halfs per matrix per buffer (9216)

template<int KDIM, bool SCORES>
__global__ void __launch_bounds__(256, 2) mma_gemm_kernel(
    const __half* __restrict__ A,
    const __half* __restrict__ B,
    float* __restrict__ C, __half* __restrict__ Ce,
    size_t aBatch, size_t bBatch, size_t cBatch, int ldc)
{
    extern __shared__ __align__(16) __half sm[];
    __half* sA = sm;                 // [2][128][72]
    __half* sB = sm + 2 * MATH;

    const int tid = threadIdx.x;
    const int lane = tid & 31;
    const int wid = tid >> 5;
    const int wm = (wid >> 2) * 64;
    const int wn = (wid & 3) * 32;
    const int l4 = lane >> 2;
    const int q2 = (lane & 3) * 2;

    const int b = blockIdx.z;
    const int m0 = blockIdx.x * 128;
    const int n0 = blockIdx.y * 128;

    const __half* gA = A + (size_t)b * aBatch;
    const __half* gB = B + (size_t)b * bBatch;

    auto load_stage = [&](int buf, int k0) {
        #pragma unroll
        for (int p = 0; p < 4; p++) {
            int idx = tid + p * 256;
            int r = idx >> 3;             // 0..127
            int c = (idx & 7) << 3;       // 0..56
            size_t ga = (size_t)(m0 + r) * KDIM + k0 + c;
            size_t gb = (size_t)(n0 + r) * KDIM + k0 + c;
            int so = buf * MATH + r * ROWLEN + c;
            CP16(smem_u32(sA + so), gA + ga);
            CP16(smem_u32(sB + so), gB + gb);
        }
        CP_COMMIT();
    };

    uint32_t aoff[4], boff[2];
    {
        const int ra = (lane & 15);
        const int ca = (lane >> 4) << 3;
        #pragma unroll
        for (int mf = 0; mf < 4; mf++)
            aoff[mf] = (uint32_t)(((wm + mf * 16 + ra) * ROWLEN + ca) * 2);
        const int rb = (lane & 7) + ((lane >> 4) & 1) * 8;
        const int cb = ((lane >> 3) & 1) << 3;
        #pragma unroll
        for (int np = 0; np < 2; np++)
            boff[np] = (uint32_t)(((wn + np * 16 + rb) * ROWLEN + cb) * 2);
    }
    const uint32_t uA = smem_u32(sA);
    const uint32_t uB = smem_u32(sB);

    float acc[4][4][4] = {};

    load_stage(0, 0);
    CP_WAIT0();
    __syncthreads();

    int buf = 0;
    for (int k0 = 0; k0 < KDIM; k0 += 64) {
        const bool has_next = (k0 + 64) < KDIM;
        if (has_next) load_stage(buf ^ 1, k0 + 64);

        #pragma unroll
        for (int kk = 0; kk < 64; kk += 16) {
            const uint32_t kb = (uint32_t)(buf * MATH * 2 + kk * 2);
            uint32_t ah[4][4];
            #pragma unroll
            for (int mf = 0; mf < 4; mf++)
                LDSM_X4(ah[mf][0], ah[mf][1], ah[mf][2], ah[mf][3], uA + kb + aoff[mf]);
            #pragma unroll
            for (int np = 0; np < 2; np++) {
                uint32_t bh[4];
                LDSM_X4(bh[0], bh[1], bh[2], bh[3], uB + kb + boff[np]);
                #pragma unroll
                for (int nf2 = 0; nf2 < 2; nf2++) {
                    const int nf = np * 2 + nf2;
                    const uint32_t b0 = bh[nf2 * 2], b1 = bh[nf2 * 2 + 1];
                    #pragma unroll
                    for (int mf = 0; mf < 4; mf++)
                        MMA_F16(acc[mf][nf], ah[mf][0], ah[mf][1], ah[mf][2], ah[mf][3], b0, b1);
                }
            }
        }

        if (has_next) CP_WAIT0();
        __syncthreads();
        buf ^= 1;
    }

    const float inv_norm = 0.04419417382415922f;   // 1/sqrt(512)

    #pragma unroll
    for (int mf = 0; mf < 4; mf++) {
        const int q0 = m0 + wm + mf * 16 + l4;
        const int q1 = q0 + 8;
        #pragma unroll
        for (int nf = 0; nf < 4; nf++) {
            const int col = n0 + wn + nf * 8 + q2;
            float* d = acc[mf][nf];
            if (SCORES) {
                __half* Eb = Ce + (size_t)b * cBatch;
                const float* qr0 = g_qrel + ((size_t)b * SQL + q0) * NRELP;
                const float* qr1 = qr0 + (size_t)8 * NRELP;
                int r00 = min(RAD, max(-RAD, col - q0)) + RAD;
                int r01 = min(RAD, max(-RAD, col + 1 - q0)) + RAD;
                int r10 = min(RAD, max(-RAD, col - q1)) + RAD;
                int r11 = min(RAD, max(-RAD, col + 1 - q1)) + RAD;
                __half2 e0 = __half2{__float2half((d[0] + qr0[r00]) * inv_norm),
                                     __float2half((d[1] + qr0[r01]) * inv_norm)};
                __half2 e1 = __half2{__float2half((d[2] + qr1[r10]) * inv_norm),
                                     __float2half((d[3] + qr1[r11]) * inv_norm)};
                *(__half2*)(Eb + (size_t)q0 * ldc + col) = e0;
                *(__half2*)(Eb + (size_t)q1 * ldc + col) = e1;
            } else {
                float* Cb = C + (size_t)b * cBatch;
                *(float2*)(Cb + (size_t)q0 * ldc + col) = make_float2(d[0], d[1]);
                *(float2*)(Cb + (size_t)q1 * ldc + col) = make_float2(d[2], d[3]);
            }
        }
    }
}

// ---------------------------------------------------------------------------
// Row softmax, vectorized: read fp16 energies from g_Ah (uint4 = 8 halves per
// thread, contiguous), write fp32 attn (d_out, 2x float4) and fp16 attn back
// into g_Ah (uint4).
// ---------------------------------------------------------------------------
__global__ void __launch_bounds__(256) softmax_split_kernel(float* __restrict__ attn) {
    __shared__ float red[8];
    const int t = threadIdx.x;
    const size_t gbase = (size_t)blockIdx.x * SKL;
    float* p = attn + gbase + t * 8;
    __half* e = g_Ah + gbase + t * 8;

    __half h[8];
    *(uint4*)h = *(const uint4*)e;

    float v[8];
    float mx = -1e30f;
    #pragma unroll
    for (int i = 0; i < 8; i++) {
        v[i] = __half2float(h[i]);
        mx = fmaxf(mx, v[i]);
    }
    #pragma unroll
    for (int o = 16; o > 0; o >>= 1) mx = fmaxf(mx, __shfl_xor_sync(0xffffffffu, mx, o));
    if ((t & 31) == 0) red[t >> 5] = mx;
    __syncthreads();
    float bmx = red[0];
    #pragma unroll
    for (int i = 1; i < 8; i++) bmx = fmaxf(bmx, red[i]);
    __syncthreads();

    float s = 0.f;
    #pragma unroll
    for (int i = 0; i < 8; i++) {
        v[i] = __expf(v[i] - bmx);
        s += v[i];
    }
    #pragma unroll
    for (int o = 16; o > 0; o >>= 1) s += __shfl_xor_sync(0xffffffffu, s, o);
    if ((t & 31) == 0) red[t >> 5] = s;
    __syncthreads();
    float tot = 0.f;
    #pragma unroll
    for (int i = 0; i < 8; i++) tot += red[i];
    const float inv = 1.0f / tot;

    float out[8];
    #pragma unroll
    for (int i = 0; i < 8; i++) {
        out[i] = v[i] * inv;
        h[i] = __float2half(out[i]);
    }
    *(float4*)(p)     = *(float4*)out;
    *(float4*)(p + 4) = *(float4*)(out + 4);
    *(uint4*)e = *(uint4*)h;
}

// ---------------------------------------------------------------------------
extern "C" void kernel_launch(void* const* d_in, const int* in_sizes, int n_in,
                              void* d_out, int out_size) {
    const float* Q  = (const float*)d_in[0];
    const float* K  = (const float*)d_in[1];
    const float* V  = (const float*)d_in[2];
    const float* RE = (const float*)d_in[3];

    float* attn = (float*)d_out;
    float* Z    = attn + (size_t)NB * SQL * SKL;

    __half *Qh, *Kh, *REh, *Vth, *Ahp;
    float* qrel;
    cudaGetSymbolAddress((void**)&Qh,  g_Qh);
    cudaGetSymbolAddress((void**)&Kh,  g_Kh);
    cudaGetSymbolAddress((void**)&REh, g_REh);
    cudaGetSymbolAddress((void**)&Vth, g_Vth);
    cudaGetSymbolAddress((void**)&Ahp, g_Ah);
    cudaGetSymbolAddress((void**)&qrel, g_qrel);

    const int SMEM_GEMM = 4 * MATH * 2;   // 73728 B
    cudaFuncSetAttribute(mma_gemm_kernel<DIM, true>,
                         cudaFuncAttributeMaxDynamicSharedMemorySize, SMEM_GEMM);
    cudaFuncSetAttribute(mma_gemm_kernel<DIM, false>,
                         cudaFuncAttributeMaxDynamicSharedMemorySize, SMEM_GEMM);
    cudaFuncSetAttribute(mma_gemm_kernel<SKL, false>,
                         cudaFuncAttributeMaxDynamicSharedMemorySize, SMEM_GEMM);

    // fp16 conversions
    split_h_kernel<<<(NB * SQL * DIM) / 2048, 256>>>(Q, Qh);
    split_h_kernel<<<(NB * SKL * DIM) / 2048, 256>>>(K, Kh);
    split_re_kernel<<<NRELP, 128>>>(RE, REh);
    {
        dim3 grid(SKL / 64, DIM / 64, NB);
        split_v_t_kernel<<<grid, 256>>>(V, Vth);
    }
    // Q_rel = Q @ RE^T  (batch folded into M)
    {
        dim3 grid((NB * SQL) / 128, NRELP / 128, 1);
        mma_gemm_kernel<DIM, false><<<grid, 256, SMEM_GEMM>>>(
            Qh, REh, qrel, nullptr, 0, 0, 0, NRELP);
    }
    // energies = (Q@K^T + relpos) / sqrt(d) -> g_Ah (fp16)
    {
        dim3 grid(SQL / 128, SKL / 128, NB);
        mma_gemm_kernel<DIM, true><<<grid, 256, SMEM_GEMM>>>(
            Qh, Kh, nullptr, Ahp,
            (size_t)SQL * DIM, (size_t)SKL * DIM, (size_t)SQL * SKL, SKL);
    }
    // softmax: fp16 energies -> fp32 attn (d_out) + fp16 attn (g_Ah, in place)
    softmax_split_kernel<<<NB * SQL, 256>>>(attn);
    // Z = attn @ V
    {
        dim3 grid(SQL / 128, DIM / 128, NB);
        mma_gemm_kernel<SKL, false><<<grid, 256, SMEM_GEMM>>>(
            Ahp, Vth, Z, nullptr,
            (size_t)SQL * SKL, (size_t)DIM * SKL, (size_t)SQL * DIM, DIM);
    }
}

// round 17
// speedup vs baseline: 1.0177x; 1.0177x over previous
#include <cuda_runtime.h>
#include <cuda_fp16.h>
#include <cstdint>

#define NB   4
#define SQL  2048
#define SKL  2048
#define DIM  512
#define RAD  128
#define NREL 257
#define NRELP 384   // padded

// ---------------- device scratch ----------------
__device__ float g_qrel[(size_t)NB * SQL * NRELP];
__device__ __half g_Qh[(size_t)NB * SQL * DIM];
__device__ __half g_Kh[(size_t)NB * SKL * DIM];
__device__ __half g_REh[(size_t)NRELP * DIM];
__device__ __half g_Vth[(size_t)NB * DIM * SKL];     // V^T
__device__ __half g_Ah[(size_t)NB * SQL * SKL];      // energies, then attn (fp16)

// ---------------- helpers ----------------
__device__ __forceinline__ uint32_t smem_u32(const void* p) {
    return (uint32_t)__cvta_generic_to_shared(p);
}

#define CP16(saddr, gptr) \
    asm volatile("cp.async.cg.shared.global [%0], [%1], 16;" :: "r"(saddr), "l"(gptr))
#define CP_COMMIT() asm volatile("cp.async.commit_group;")
#define CP_WAIT0()  asm volatile("cp.async.wait_group 0;" ::: "memory")

#define MMA_F16(d, a0, a1, a2, a3, b0, b1)                                        \
    asm volatile(                                                                 \
        "mma.sync.aligned.m16n8k16.row.col.f32.f16.f16.f32 "                      \
        "{%0,%1,%2,%3},{%4,%5,%6,%7},{%8,%9},{%0,%1,%2,%3};"                      \
        : "+f"((d)[0]), "+f"((d)[1]), "+f"((d)[2]), "+f"((d)[3])                  \
        : "r"(a0), "r"(a1), "r"(a2), "r"(a3), "r"(b0), "r"(b1))

#define LDSM_X4(r0, r1, r2, r3, addr)                                             \
    asm volatile("ldmatrix.sync.aligned.m8n8.x4.shared.b16 {%0,%1,%2,%3},[%4];"   \
        : "=r"(r0), "=r"(r1), "=r"(r2), "=r"(r3) : "r"(addr))

// ---------------------------------------------------------------------------
// fp32 -> fp16, 8 elems/thread vectorized (Q, K)
// ---------------------------------------------------------------------------
__global__ void __launch_bounds__(256) split_h_kernel(const float* __restrict__ x,
                                                      __half* __restrict__ hi) {
    const size_t i = ((size_t)blockIdx.x * 256 + threadIdx.x) * 8;
    float4 v0 = *(const float4*)(x + i);
    float4 v1 = *(const float4*)(x + i + 4);
    __half h[8];
    h[0] = __float2half(v0.x); h[1] = __float2half(v0.y);
    h[2] = __float2half(v0.z); h[3] = __float2half(v0.w);
    h[4] = __float2half(v1.x); h[5] = __float2half(v1.y);
    h[6] = __float2half(v1.z); h[7] = __float2half(v1.w);
    *(uint4*)(hi + i) = *(uint4*)h;
}

// RE [257,512] -> padded [384,512] (rows >=257 zero)
__global__ void __launch_bounds__(128) split_re_kernel(const float* __restrict__ RE,
                                                       __half* __restrict__ REh) {
    const int row = blockIdx.x;
    const int c = threadIdx.x * 4;
    __half h[4] = {};
    if (row < NREL) {
        float4 v = *(const float4*)(RE + (size_t)row * DIM + c);
        h[0] = __float2half(v.x); h[1] = __float2half(v.y);
        h[2] = __float2half(v.z); h[3] = __float2half(v.w);
    }
    *(float2*)(REh + (size_t)row * DIM + c) = *(float2*)h;
}

// ---------------------------------------------------------------------------
// V [b][k][n] -> Vt [b][n][k] fp16, 64x64 tile, vectorized
// ---------------------------------------------------------------------------
__global__ void __launch_bounds__(256) split_v_t_kernel(const float* __restrict__ V,
                                                        __half* __restrict__ Vth) {
    __shared__ float t[64][65];
    const int b = blockIdx.z;
    const int k0 = blockIdx.x * 64;
    const int n0 = blockIdx.y * 64;
    const int tid = threadIdx.x;
    const float* Vb = V + (size_t)b * SKL * DIM;

    #pragma unroll
    for (int p = 0; p < 4; p++) {
        int task = tid + p * 256;
        int k = task >> 4;
        int c4 = (task & 15) << 2;
        float4 v = *(const float4*)(Vb + (size_t)(k0 + k) * DIM + n0 + c4);
        t[k][c4] = v.x; t[k][c4 + 1] = v.y; t[k][c4 + 2] = v.z; t[k][c4 + 3] = v.w;
    }
    __syncthreads();

    __half* out = Vth + (size_t)b * DIM * SKL;
    #pragma unroll
    for (int p = 0; p < 2; p++) {
        int task = tid + p * 256;
        int n = task >> 3;
        int kg = (task & 7) << 3;
        __half h[8];
        #pragma unroll
        for (int r = 0; r < 8; r++) h[r] = __float2half(t[kg + r][n]);
        *(uint4*)(out + (size_t)(n0 + n) * SKL + k0 + kg) = *(uint4*)h;
    }
}

// ---------------------------------------------------------------------------
// Tensor-core GEMM, fp16, 1 term: C[m][n] = sum_k A[m,k]*B[n,k]
// 128x128x64 stages, 8 warps (warp 64x32), 2 CTA/SM, cp.async double buffer.
// Row pad 72 elems (144 B): 8 rows cover all 32 banks -> LDSM conflict-free.
// SCORES: writes fp16 energies (with relpos + scale) to Ce. Else fp32 to C.
// ---------------------------------------------------------------------------
#define ROWLEN 72
#define MATH   (128 * ROWLEN)          // halfs per matrix per buffer (9216)

template<int KDIM, bool SCORES>
__global__ void __launch_bounds__(256, 2) mma_gemm_kernel(
    const __half* __restrict__ A,
    const __half* __restrict__ B,
    float* __restrict__ C, __half* __restrict__ Ce,
    size_t aBatch, size_t bBatch, size_t cBatch, int ldc)
{
    extern __shared__ __align__(16) __half sm[];
    __half* sA = sm;                 // [2][128][72]
    __half* sB = sm + 2 * MATH;

    const int tid = threadIdx.x;
    const int lane = tid & 31;
    const int wid = tid >> 5;
    const int wm = (wid >> 2) * 64;
    const int wn = (wid & 3) * 32;
    const int l4 = lane >> 2;
    const int q2 = (lane & 3) * 2;

    const int b = blockIdx.z;
    const int m0 = blockIdx.x * 128;
    const int n0 = blockIdx.y * 128;

    const __half* gA = A + (size_t)b * aBatch;
    const __half* gB = B + (size_t)b * bBatch;

    auto load_stage = [&](int buf, int k0) {
        #pragma unroll
        for (int p = 0; p < 4; p++) {
            int idx = tid + p * 256;
            int r = idx >> 3;             // 0..127
            int c = (idx & 7) << 3;       // 0..56
            size_t ga = (size_t)(m0 + r) * KDIM + k0 + c;
            size_t gb = (size_t)(n0 + r) * KDIM + k0 + c;
            int so = buf * MATH + r * ROWLEN + c;
            CP16(smem_u32(sA + so), gA + ga);
            CP16(smem_u32(sB + so), gB + gb);
        }
        CP_COMMIT();
    };

    uint32_t aoff[4], boff[2];
    {
        const int ra = (lane & 15);
        const int ca = (lane >> 4) << 3;
        #pragma unroll
        for (int mf = 0; mf < 4; mf++)
            aoff[mf] = (uint32_t)(((wm + mf * 16 + ra) * ROWLEN + ca) * 2);
        const int rb = (lane & 7) + ((lane >> 4) & 1) * 8;
        const int cb = ((lane >> 3) & 1) << 3;
        #pragma unroll
        for (int np = 0; np < 2; np++)
            boff[np] = (uint32_t)(((wn + np * 16 + rb) * ROWLEN + cb) * 2);
    }
    const uint32_t uA = smem_u32(sA);
    const uint32_t uB = smem_u32(sB);

    float acc[4][4][4] = {};

    load_stage(0, 0);
    CP_WAIT0();
    __syncthreads();

    int buf = 0;
    for (int k0 = 0; k0 < KDIM; k0 += 64) {
        const bool has_next = (k0 + 64) < KDIM;
        if (has_next) load_stage(buf ^ 1, k0 + 64);

        #pragma unroll
        for (int kk = 0; kk < 64; kk += 16) {
            const uint32_t kb = (uint32_t)(buf * MATH * 2 + kk * 2);
            uint32_t ah[4][4];
            #pragma unroll
            for (int mf = 0; mf < 4; mf++)
                LDSM_X4(ah[mf][0], ah[mf][1], ah[mf][2], ah[mf][3], uA + kb + aoff[mf]);
            #pragma unroll
            for (int np = 0; np < 2; np++) {
                uint32_t bh[4];
                LDSM_X4(bh[0], bh[1], bh[2], bh[3], uB + kb + boff[np]);
                #pragma unroll
                for (int nf2 = 0; nf2 < 2; nf2++) {
                    const int nf = np * 2 + nf2;
                    const uint32_t b0 = bh[nf2 * 2], b1 = bh[nf2 * 2 + 1];
                    #pragma unroll
                    for (int mf = 0; mf < 4; mf++)
                        MMA_F16(acc[mf][nf], ah[mf][0], ah[mf][1], ah[mf][2], ah[mf][3], b0, b1);
                }
            }
        }

        if (has_next) CP_WAIT0();
        __syncthreads();
        buf ^= 1;
    }

    const float inv_norm = 0.04419417382415922f;   // 1/sqrt(512)

    #pragma unroll
    for (int mf = 0; mf < 4; mf++) {
        const int q0 = m0 + wm + mf * 16 + l4;
        const int q1 = q0 + 8;
        #pragma unroll
        for (int nf = 0; nf < 4; nf++) {
            const int col = n0 + wn + nf * 8 + q2;
            float* d = acc[mf][nf];
            if (SCORES) {
                __half* Eb = Ce + (size_t)b * cBatch;
                const float* qr0 = g_qrel + ((size_t)b * SQL + q0) * NRELP;
                const float* qr1 = qr0 + (size_t)8 * NRELP;
                int r00 = min(RAD, max(-RAD, col - q0)) + RAD;
                int r01 = min(RAD, max(-RAD, col + 1 - q0)) + RAD;
                int r10 = min(RAD, max(-RAD, col - q1)) + RAD;
                int r11 = min(RAD, max(-RAD, col + 1 - q1)) + RAD;
                __half2 e0 = __half2{__float2half((d[0] + qr0[r00]) * inv_norm),
                                     __float2half((d[1] + qr0[r01]) * inv_norm)};
                __half2 e1 = __half2{__float2half((d[2] + qr1[r10]) * inv_norm),
                                     __float2half((d[3] + qr1[r11]) * inv_norm)};
                *(__half2*)(Eb + (size_t)q0 * ldc + col) = e0;
                *(__half2*)(Eb + (size_t)q1 * ldc + col) = e1;
            } else {
                float* Cb = C + (size_t)b * cBatch;
                *(float2*)(Cb + (size_t)q0 * ldc + col) = make_float2(d[0], d[1]);
                *(float2*)(Cb + (size_t)q1 * ldc + col) = make_float2(d[2], d[3]);
            }
        }
    }
}

// ---------------------------------------------------------------------------
// Row softmax (scalar strided — already coalesced): fp16 energies -> fp32 attn
// (d_out) + fp16 attn back into g_Ah (in place).
// ---------------------------------------------------------------------------
__global__ void __launch_bounds__(256) softmax_split_kernel(float* __restrict__ attn) {
    __shared__ float red[8];
    float* p = attn + (size_t)blockIdx.x * SKL;
    const size_t gbase = (size_t)blockIdx.x * SKL;
    const int t = threadIdx.x;

    float v[8];
    float mx = -1e30f;
    #pragma unroll
    for (int i = 0; i < 8; i++) {
        v[i] = __half2float(g_Ah[gbase + t + i * 256]);
        mx = fmaxf(mx, v[i]);
    }
    #pragma unroll
    for (int o = 16; o > 0; o >>= 1) mx = fmaxf(mx, __shfl_xor_sync(0xffffffffu, mx, o));
    if ((t & 31) == 0) red[t >> 5] = mx;
    __syncthreads();
    float bmx = red[0];
    #pragma unroll
    for (int i = 1; i < 8; i++) bmx = fmaxf(bmx, red[i]);
    __syncthreads();

    float s = 0.f;
    #pragma unroll
    for (int i = 0; i < 8; i++) {
        v[i] = __expf(v[i] - bmx);
        s += v[i];
    }
    #pragma unroll
    for (int o = 16; o > 0; o >>= 1) s += __shfl_xor_sync(0xffffffffu, s, o);
    if ((t & 31) == 0) red[t >> 5] = s;
    __syncthreads();
    float tot = 0.f;
    #pragma unroll
    for (int i = 0; i < 8; i++) tot += red[i];
    const float inv = 1.0f / tot;

    #pragma unroll
    for (int i = 0; i < 8; i++) {
        float val = v[i] * inv;
        p[t + i * 256] = val;
        g_Ah[gbase + t + i * 256] = __float2half(val);
    }
}

// ---------------------------------------------------------------------------
extern "C" void kernel_launch(void* const* d_in, const int* in_sizes, int n_in,
                              void* d_out, int out_size) {
    const float* Q  = (const float*)d_in[0];
    const float* K  = (const float*)d_in[1];
    const float* V  = (const float*)d_in[2];
    const float* RE = (const float*)d_in[3];

    float* attn = (float*)d_out;
    float* Z    = attn + (size_t)NB * SQL * SKL;

    __half *Qh, *Kh, *REh, *Vth, *Ahp;
    float* qrel;
    cudaGetSymbolAddress((void**)&Qh,  g_Qh);
    cudaGetSymbolAddress((void**)&Kh,  g_Kh);
    cudaGetSymbolAddress((void**)&REh, g_REh);
    cudaGetSymbolAddress((void**)&Vth, g_Vth);
    cudaGetSymbolAddress((void**)&Ahp, g_Ah);
    cudaGetSymbolAddress((void**)&qrel, g_qrel);

    const int SMEM_GEMM = 4 * MATH * 2;   // 73728 B
    cudaFuncSetAttribute(mma_gemm_kernel<DIM, true>,
                         cudaFuncAttributeMaxDynamicSharedMemorySize, SMEM_GEMM);
    cudaFuncSetAttribute(mma_gemm_kernel<DIM, false>,
                         cudaFuncAttributeMaxDynamicSharedMemorySize, SMEM_GEMM);
    cudaFuncSetAttribute(mma_gemm_kernel<SKL, false>,
                         cudaFuncAttributeMaxDynamicSharedMemorySize, SMEM_GEMM);

    // Fork a side stream (fresh handles each call; identical work every call).
    cudaStream_t s2;
    cudaEvent_t eFork, eK, eV;
    cudaStreamCreateWithFlags(&s2, cudaStreamNonBlocking);
    cudaEventCreateWithFlags(&eFork, cudaEventDisableTiming);
    cudaEventCreateWithFlags(&eK, cudaEventDisableTiming);
    cudaEventCreateWithFlags(&eV, cudaEventDisableTiming);

    // fork: side stream does K-split and V-transpose
    cudaEventRecord(eFork, 0);
    cudaStreamWaitEvent(s2, eFork, 0);

    split_h_kernel<<<(NB * SKL * DIM) / 2048, 256, 0, s2>>>(K, Kh);
    cudaEventRecord(eK, s2);
    {
        dim3 grid(SKL / 64, DIM / 64, NB);
        split_v_t_kernel<<<grid, 256, 0, s2>>>(V, Vth);
    }
    cudaEventRecord(eV, s2);

    // main chain: Q split, RE split, qrel GEMM
    split_h_kernel<<<(NB * SQL * DIM) / 2048, 256>>>(Q, Qh);
    split_re_kernel<<<NRELP, 128>>>(RE, REh);
    {
        dim3 grid((NB * SQL) / 128, NRELP / 128, 1);
        mma_gemm_kernel<DIM, false><<<grid, 256, SMEM_GEMM>>>(
            Qh, REh, qrel, nullptr, 0, 0, 0, NRELP);
    }

    // join K before scores
    cudaStreamWaitEvent(0, eK, 0);
    // energies = (Q@K^T + relpos) / sqrt(d) -> g_Ah (fp16)
    {
        dim3 grid(SQL / 128, SKL / 128, NB);
        mma_gemm_kernel<DIM, true><<<grid, 256, SMEM_GEMM>>>(
            Qh, Kh, nullptr, Ahp,
            (size_t)SQL * DIM, (size_t)SKL * DIM, (size_t)SQL * SKL, SKL);
    }
    // softmax: fp16 energies -> fp32 attn (d_out) + fp16 attn (g_Ah, in place)
    softmax_split_kernel<<<NB * SQL, 256>>>(attn);

    // join V before AV
    cudaStreamWaitEvent(0, eV, 0);
    // Z = attn @ V
    {
        dim3 grid(SQL / 128, DIM / 128, NB);
        mma_gemm_kernel<SKL, false><<<grid, 256, SMEM_GEMM>>>(
            Ahp, Vth, Z, nullptr,
            (size_t)SQL * SKL, (size_t)DIM * SKL, (size_t)SQL * DIM, DIM);
    }
}